// round 1
// baseline (speedup 1.0000x reference)
#include <cuda_runtime.h>

// Flash attention, fp32 SIMT (round 0 baseline).
// B=2, S_q=2048, H=16, D=128, S_kv = W*S = 8192 (derived from in_sizes).
// Layouts: q [B,Sq,H,D], k/v [B,Skv,H,D], out [B,Sq,H,D] (all fp32).
// The reference's ring/online-softmax loop equals exact full softmax attention,
// so a single flash pass reproduces it to ~1e-6.

namespace {

constexpr int B  = 2;
constexpr int S  = 2048;
constexpr int H  = 16;
constexpr int DH = 128;

constexpr int BM = 64;    // Q rows per CTA
constexpr int BN = 64;    // KV rows per tile
constexpr int NT = 256;   // threads per CTA (16 x 16)

// smem row strides (floats), padded for bank-conflict avoidance
constexpr int QT_S = 65;   // Qt[d][m], transposed
constexpr int KT_S = 65;   // Kt[d][n], transposed
constexpr int VS_S = 132;  // Vs[n][d], natural (16B-aligned rows)
constexpr int PS_S = 65;   // Ps[m][n]

constexpr int SMEM_FLOATS = DH * QT_S + DH * KT_S + BN * VS_S + BM * PS_S;
constexpr int SMEM_BYTES  = SMEM_FLOATS * 4;   // 116,992 B

constexpr float SCALE = 0.08838834764831845f;  // 1/sqrt(128)

__global__ __launch_bounds__(NT, 1)
void fa_fp32(const float* __restrict__ qg, const float* __restrict__ kg,
             const float* __restrict__ vg, float* __restrict__ out, int skv)
{
    extern __shared__ float sm[];
    float* Qt = sm;                       // [DH][QT_S]
    float* Kt = Qt + DH * QT_S;           // [DH][KT_S]
    float* Vs = Kt + DH * KT_S;           // [BN][VS_S]
    float* Ps = Vs + BN * VS_S;           // [BM][PS_S]

    const int tid = threadIdx.x;
    const int tx  = tid & 15;             // col group
    const int ty  = tid >> 4;             // row group
    const int qtile = blockIdx.x;
    const int b = blockIdx.y >> 4;        // H == 16
    const int h = blockIdx.y & 15;

    const size_t rs = (size_t)H * DH;     // row stride in floats (2048)
    const float* qp = qg + ((size_t)b * S + (size_t)qtile * BM) * rs + (size_t)h * DH;
    const float* kp = kg + (size_t)b * skv * rs + (size_t)h * DH;
    const float* vp = vg + (size_t)b * skv * rs + (size_t)h * DH;

    // ---- load Q tile once, transposed into Qt[d][m] ----
    #pragma unroll
    for (int t = 0; t < (BM * DH / 4) / NT; t++) {     // 8 iters
        int idx = tid + t * NT;
        int row = idx >> 5;                            // 0..63
        int d4  = (idx & 31) * 4;                      // 0..124 step 4
        float4 f = *reinterpret_cast<const float4*>(qp + (size_t)row * rs + d4);
        Qt[(d4 + 0) * QT_S + row] = f.x;
        Qt[(d4 + 1) * QT_S + row] = f.y;
        Qt[(d4 + 2) * QT_S + row] = f.z;
        Qt[(d4 + 3) * QT_S + row] = f.w;
    }

    // per-thread online-softmax state
    float m_run[4], l_run[4], oacc[4][8];
    #pragma unroll
    for (int i = 0; i < 4; i++) {
        m_run[i] = -3.0e38f;
        l_run[i] = 0.0f;
        #pragma unroll
        for (int j = 0; j < 8; j++) oacc[i][j] = 0.0f;
    }

    const int ntiles = skv / BN;
    for (int tile = 0; tile < ntiles; tile++) {
        const float* kt = kp + (size_t)tile * BN * rs;
        const float* vt = vp + (size_t)tile * BN * rs;

        // ---- stage K (transposed) and V (natural) ----
        #pragma unroll
        for (int t = 0; t < (BN * DH / 4) / NT; t++) { // 8 iters
            int idx = tid + t * NT;
            int row = idx >> 5;
            int d4  = (idx & 31) * 4;
            float4 f = *reinterpret_cast<const float4*>(kt + (size_t)row * rs + d4);
            Kt[(d4 + 0) * KT_S + row] = f.x;
            Kt[(d4 + 1) * KT_S + row] = f.y;
            Kt[(d4 + 2) * KT_S + row] = f.z;
            Kt[(d4 + 3) * KT_S + row] = f.w;
            float4 g = *reinterpret_cast<const float4*>(vt + (size_t)row * rs + d4);
            *reinterpret_cast<float4*>(Vs + row * VS_S + d4) = g;
        }
        __syncthreads();

        // ---- S = Q @ K^T (64x64, k over 128) ----
        float acc[4][4];
        #pragma unroll
        for (int i = 0; i < 4; i++)
            #pragma unroll
            for (int j = 0; j < 4; j++) acc[i][j] = 0.0f;

        #pragma unroll 8
        for (int kk = 0; kk < DH; kk++) {
            float qf[4], kf[4];
            #pragma unroll
            for (int i = 0; i < 4; i++) qf[i] = Qt[kk * QT_S + ty + 16 * i];
            #pragma unroll
            for (int j = 0; j < 4; j++) kf[j] = Kt[kk * KT_S + tx + 16 * j];
            #pragma unroll
            for (int i = 0; i < 4; i++)
                #pragma unroll
                for (int j = 0; j < 4; j++)
                    acc[i][j] = fmaf(qf[i], kf[j], acc[i][j]);
        }

        // ---- online softmax; write P to smem ----
        #pragma unroll
        for (int i = 0; i < 4; i++) {
            float mx = -3.0e38f;
            #pragma unroll
            for (int j = 0; j < 4; j++) {
                acc[i][j] *= SCALE;
                mx = fmaxf(mx, acc[i][j]);
            }
            // row max across the 16 threads of this row group (lanes share bit4=ty&1)
            #pragma unroll
            for (int o = 8; o >= 1; o >>= 1)
                mx = fmaxf(mx, __shfl_xor_sync(0xffffffffu, mx, o));

            float mnew  = fmaxf(m_run[i], mx);
            float alpha = __expf(m_run[i] - mnew);

            float ls = 0.0f;
            #pragma unroll
            for (int j = 0; j < 4; j++) {
                float p = __expf(acc[i][j] - mnew);
                Ps[(ty + 16 * i) * PS_S + tx + 16 * j] = p;
                ls += p;
            }
            #pragma unroll
            for (int o = 8; o >= 1; o >>= 1)
                ls += __shfl_xor_sync(0xffffffffu, ls, o);

            l_run[i] = l_run[i] * alpha + ls;
            m_run[i] = mnew;
            #pragma unroll
            for (int j = 0; j < 8; j++) oacc[i][j] *= alpha;
        }
        __syncthreads();

        // ---- O += P @ V (64x128, n over 64) ----
        #pragma unroll 4
        for (int n = 0; n < BN; n++) {
            float pf[4], vf[8];
            #pragma unroll
            for (int i = 0; i < 4; i++) pf[i] = Ps[(ty + 16 * i) * PS_S + n];
            #pragma unroll
            for (int j = 0; j < 8; j++) vf[j] = Vs[n * VS_S + tx + 16 * j];
            #pragma unroll
            for (int i = 0; i < 4; i++)
                #pragma unroll
                for (int j = 0; j < 8; j++)
                    oacc[i][j] = fmaf(pf[i], vf[j], oacc[i][j]);
        }
        __syncthreads();   // PV reads done before next tile overwrites smem
    }

    // ---- epilogue: normalize and store ----
    float* op = out + ((size_t)b * S + (size_t)qtile * BM) * rs + (size_t)h * DH;
    #pragma unroll
    for (int i = 0; i < 4; i++) {
        float inv = 1.0f / l_run[i];
        #pragma unroll
        for (int j = 0; j < 8; j++)
            op[(size_t)(ty + 16 * i) * rs + tx + 16 * j] = oacc[i][j] * inv;
    }
}

} // namespace

extern "C" void kernel_launch(void* const* d_in, const int* in_sizes, int n_in,
                              void* d_out, int out_size)
{
    const float* q = (const float*)d_in[0];
    const float* k = (const float*)d_in[1];
    const float* v = (const float*)d_in[2];
    float* out = (float*)d_out;

    // k is [B, Skv, H, D] -> derive Skv (W*S) from element count
    const int skv = in_sizes[1] / (B * H * DH);

    cudaFuncSetAttribute(fa_fp32, cudaFuncAttributeMaxDynamicSharedMemorySize, SMEM_BYTES);

    dim3 grid(S / BM, B * H);
    fa_fp32<<<grid, NT, SMEM_BYTES>>>(q, k, v, out, skv);
}